// round 6
// baseline (speedup 1.0000x reference)
#include <cuda_runtime.h>
#include <cuda_bf16.h>
#include <math.h>

// ---------------------------------------------------------------------------
// VectorQuantizer for GB300 (sm_103a)
//   z:            [32,4096,256] f32  -> N=131072 tokens, D=256
//   embed_weight: [1024,256]    f32  -> K=1024 codes
// Outputs (concatenated f32): z_q_st [N*256], loss [1], perplexity [1],
//                             encoding_indices [N] (as float)
//
// Pipeline:
//   prep_kernel:  normalize codebook rows -> g_cnT [D][K] (transposed),
//                 zero histogram
//   vq_main:      tiled argmax-GEMM (fp32, fma.rn.f32x2 packed pipe)
//                 + fused gather/STE output + loss partial + histogram
//   finalize:     loss & perplexity scalars
// ---------------------------------------------------------------------------

#define D_DIM 256
#define KD    32            // d-chunk per B stage
#define TM    128           // tokens per block
#define TN    128           // codes per tile

// scratch (static device memory only; no allocations allowed)
__device__ float g_cnT[D_DIM * 1024];     // normalized codebook, transposed [d][k]
__device__ int   g_counts[1024];
__device__ float g_partial[4096];         // per-block sum((q-z)^2)

// ---------------- codebook prep ----------------
__global__ void prep_kernel(const float* __restrict__ w, int K) {
    int k = blockIdx.x;          // one block per codebook row
    int tid = threadIdx.x;       // 256 threads = D
    float v = w[(size_t)k * D_DIM + tid];
    float s = v * v;
    #pragma unroll
    for (int o = 16; o; o >>= 1) s += __shfl_xor_sync(0xffffffffu, s, o);
    __shared__ float ws[8];
    int lane = tid & 31, warp = tid >> 5;
    if (lane == 0) ws[warp] = s;
    __syncthreads();
    if (tid == 0) {
        float t = 0.f;
        #pragma unroll
        for (int i = 0; i < 8; i++) t += ws[i];
        ws[0] = t;
    }
    __syncthreads();
    float denom = fmaxf(sqrtf(ws[0]), 1e-12f);
    g_cnT[(size_t)tid * K + k] = v / denom;
    if (tid == 0) g_counts[k] = 0;
}

// ---------------- helpers ----------------
__device__ __forceinline__ void cp16(void* dst_smem, const void* src_gmem) {
    unsigned sdst = (unsigned)__cvta_generic_to_shared(dst_smem);
    asm volatile("cp.async.cg.shared.global [%0], [%1], 16;\n"
                 :: "r"(sdst), "l"(src_gmem));
}
__device__ __forceinline__ void cp_commit() {
    asm volatile("cp.async.commit_group;\n" ::: "memory");
}
__device__ __forceinline__ void cp_waitall() {
    asm volatile("cp.async.wait_all;\n" ::: "memory");
}

#define FMA2(ACC, AA, BB) \
    asm("fma.rn.f32x2 %0, %1, %2, %0;" : "+l"(ACC) : "l"(AA), "l"(BB))

// ---------------- main fused kernel ----------------
// dynamic smem layout (floats):
//   As:    [256][128]          32768
//   Bs:    [2][32][128]         8192   (reused as reduction scratch at end)
//   idx_s: [128] ints            128
#define SMEM_FLOATS (32768 + 8192 + 128)

__global__ __launch_bounds__(256, 1)
void vq_main(const float* __restrict__ z, const float* __restrict__ w,
             float* __restrict__ out_zq, float* __restrict__ out_idx, int K) {
    extern __shared__ float sm[];
    float* As    = sm;
    float* Bs    = sm + 32768;
    int*   idx_s = (int*)(sm + 32768 + 8192);
    float* red_s = Bs;                 // [128][16]
    int*   red_i = (int*)(Bs + 2048);  // [128][16]

    const int tid  = threadIdx.x;
    const int lane = tid & 31, warp = tid >> 5;
    const int bx = lane & 7, by = lane >> 3;
    const int wm = warp >> 1, wn = warp & 1;
    const int tm0 = wm * 32 + by * 8;      // first of this thread's 8 tokens
    const int cn0 = wn * 64 + bx * 4;      // first of this thread's codes (4 + 4@+32)

    // ---- load A tile (transposed to [d][token]) ----
    {
        const int t = tid & 127, half = tid >> 7;
        const float4* zrow =
            (const float4*)(z + (size_t)blockIdx.x * (TM * D_DIM) + (size_t)t * D_DIM + half * 128);
        #pragma unroll
        for (int i = 0; i < 32; i++) {
            float4 v = zrow[i];
            int d = half * 128 + i * 4;
            As[(d + 0) * 128 + t] = v.x;
            As[(d + 1) * 128 + t] = v.y;
            As[(d + 2) * 128 + t] = v.z;
            As[(d + 3) * 128 + t] = v.w;
        }
    }

    // ---- B chunk loader: Bs[buf][dd][c] <- g_cnT[(kd*32+dd)][ct*128 + c] ----
    auto loadB = [&](int ct, int kd, int b) {
        #pragma unroll
        for (int k4 = 0; k4 < 4; k4++) {
            int m   = tid + k4 * 256;       // 1024 x 16B chunks
            int row = m >> 5;               // 0..31
            int c16 = m & 31;               // 16B chunk within row
            cp16(Bs + b * 4096 + row * 128 + c16 * 4,
                 g_cnT + (size_t)(kd * 32 + row) * K + ct * 128 + c16 * 4);
        }
    };

    float best[8];
    int   bidx[8];
    #pragma unroll
    for (int i = 0; i < 8; i++) { best[i] = -3.4e38f; bidx[i] = 0; }

    const int ntile = K >> 7;
    int buf = 0;

    // preload first chunk (also covers the A-store barrier)
    loadB(0, 0, buf);
    cp_commit();
    cp_waitall();
    __syncthreads();

    for (int ct = 0; ct < ntile; ct++) {
        unsigned long long acc[8][4];
        #pragma unroll
        for (int i = 0; i < 8; i++)
            #pragma unroll
            for (int p = 0; p < 4; p++) acc[i][p] = 0ull;

        for (int kd = 0; kd < D_DIM / KD; kd++) {
            // stage next chunk (next kd, or next tile's chunk 0)
            if (kd < D_DIM / KD - 1)      loadB(ct, kd + 1, buf ^ 1);
            else if (ct + 1 < ntile)      loadB(ct + 1, 0, buf ^ 1);
            cp_commit();

            // compute on current buffer
            #pragma unroll
            for (int dd = 0; dd < KD; dd++) {
                const float* ar = As + (kd * KD + dd) * 128;
                float4 a0 = *(const float4*)(ar + tm0);
                float4 a1 = *(const float4*)(ar + tm0 + 4);
                const float* br = Bs + buf * 4096 + dd * 128;
                ulonglong2 b0 = *(const ulonglong2*)(br + cn0);
                ulonglong2 b1 = *(const ulonglong2*)(br + cn0 + 32);
                float av[8] = {a0.x, a0.y, a0.z, a0.w, a1.x, a1.y, a1.z, a1.w};
                #pragma unroll
                for (int i = 0; i < 8; i++) {
                    unsigned long long aa;
                    asm("mov.b64 %0, {%1, %1};" : "=l"(aa) : "r"(__float_as_uint(av[i])));
                    FMA2(acc[i][0], aa, b0.x);
                    FMA2(acc[i][1], aa, b0.y);
                    FMA2(acc[i][2], aa, b1.x);
                    FMA2(acc[i][3], aa, b1.y);
                }
            }
            cp_waitall();
            __syncthreads();
            buf ^= 1;
        }

        // fold this tile's 8 codes/token into the running argmax
        #pragma unroll
        for (int i = 0; i < 8; i++) {
            #pragma unroll
            for (int p = 0; p < 4; p++) {
                float lo = __uint_as_float((unsigned)(acc[i][p] & 0xffffffffull));
                float hi = __uint_as_float((unsigned)(acc[i][p] >> 32));
                int cb = ct * 128 + cn0 + ((p < 2) ? p * 2 : 32 + (p - 2) * 2);
                if (lo > best[i] || (lo == best[i] && cb < bidx[i])) { best[i] = lo; bidx[i] = cb; }
                if (hi > best[i] || (hi == best[i] && cb + 1 < bidx[i])) { best[i] = hi; bidx[i] = cb + 1; }
            }
        }
    }

    // ---- cross-thread argmax reduction (16 threads share each token) ----
    const int slot = wn * 8 + bx;
    #pragma unroll
    for (int i = 0; i < 8; i++) {
        int t = tm0 + i;
        red_s[t * 16 + slot] = best[i];
        red_i[t * 16 + slot] = bidx[i];
    }
    __syncthreads();
    if (tid < 128) {
        float bs = -3.4e38f; int bi = 0;
        #pragma unroll
        for (int s = 0; s < 16; s++) {
            float v = red_s[tid * 16 + s];
            int   id = red_i[tid * 16 + s];
            if (v > bs || (v == bs && id < bi)) { bs = v; bi = id; }
        }
        size_t gt = (size_t)blockIdx.x * TM + tid;
        out_idx[gt] = (float)bi;
        atomicAdd(&g_counts[bi], 1);
        idx_s[tid] = bi;
    }
    __syncthreads();

    // ---- fused gather + STE output + loss partial ----
    float ls = 0.f;
    {
        const int t = tid >> 1, dh = tid & 1;
        const int gi = idx_s[t];
        const float4* wrow = (const float4*)(w + (size_t)gi * D_DIM + dh * 128);
        float4* orow = (float4*)(out_zq + ((size_t)blockIdx.x * TM + t) * D_DIM + dh * 128);
        #pragma unroll
        for (int i = 0; i < 32; i++) {
            float4 q = wrow[i];
            int d = dh * 128 + i * 4;
            float z0 = As[(d + 0) * 128 + t];
            float z1 = As[(d + 1) * 128 + t];
            float z2 = As[(d + 2) * 128 + t];
            float z3 = As[(d + 3) * 128 + t];
            float e0 = q.x - z0, e1 = q.y - z1, e2 = q.z - z2, e3 = q.w - z3;
            float4 o; o.x = z0 + e0; o.y = z1 + e1; o.z = z2 + e2; o.w = z3 + e3;
            orow[i] = o;
            ls += e0 * e0 + e1 * e1 + e2 * e2 + e3 * e3;
        }
    }
    // block-reduce ls -> g_partial[block]
    #pragma unroll
    for (int o = 16; o; o >>= 1) ls += __shfl_xor_sync(0xffffffffu, ls, o);
    __syncthreads();
    if (lane == 0) red_s[warp] = ls;
    __syncthreads();
    if (tid == 0) {
        float t = 0.f;
        #pragma unroll
        for (int i = 0; i < 8; i++) t += red_s[i];
        g_partial[blockIdx.x] = t;
    }
}

// ---------------- finalize: loss + perplexity ----------------
__global__ void finalize_kernel(float* __restrict__ out_sc, int N, int K, int nblk) {
    __shared__ float sh[1024];
    int tid = threadIdx.x;

    // loss
    float s = (tid < nblk) ? g_partial[tid] : 0.f;
    sh[tid] = s;
    __syncthreads();
    for (int st = 512; st; st >>= 1) {
        if (tid < st) sh[tid] += sh[tid + st];
        __syncthreads();
    }
    float S = sh[0];
    __syncthreads();

    // entropy
    float e = 0.f;
    if (tid < K) {
        float p = (float)g_counts[tid] / (float)N;
        e = p * logf(p + 1e-10f);
    }
    sh[tid] = e;
    __syncthreads();
    for (int st = 512; st; st >>= 1) {
        if (tid < st) sh[tid] += sh[tid + st];
        __syncthreads();
    }
    if (tid == 0) {
        out_sc[0] = 1.25f * S / ((float)N * (float)D_DIM);  // beta*mse + mse
        out_sc[1] = expf(-sh[0]);
    }
}

// ---------------- launch ----------------
extern "C" void kernel_launch(void* const* d_in, const int* in_sizes, int n_in,
                              void* d_out, int out_size) {
    const float* z = (const float*)d_in[0];
    const float* w = (const float*)d_in[1];
    const int n_z = in_sizes[0];          // N * 256
    const int n_w = in_sizes[1];          // K * 256
    const int N = n_z / D_DIM;
    const int K = n_w / D_DIM;
    const int nblk = N / TM;

    float* out = (float*)d_out;
    float* out_zq  = out;                 // [N*256]
    float* out_sc  = out + n_z;           // loss, perplexity
    float* out_idx = out + n_z + 2;       // [N] indices as float

    prep_kernel<<<K, 256>>>(w, K);

    cudaFuncSetAttribute(vq_main, cudaFuncAttributeMaxDynamicSharedMemorySize,
                         SMEM_FLOATS * (int)sizeof(float));
    vq_main<<<nblk, 256, SMEM_FLOATS * sizeof(float)>>>(z, w, out_zq, out_idx, K);

    finalize_kernel<<<1, 1024>>>(out_sc, N, K, nblk);
}

// round 10
// speedup vs baseline: 1.8821x; 1.8821x over previous
#include <cuda_runtime.h>
#include <cuda_fp16.h>
#include <math.h>
#include <stdint.h>

// ---------------------------------------------------------------------------
// VectorQuantizer for GB300 (sm_103a, built as plain sm_103 -> no tcgen05)
//   z:            [32,4096,256] f32  -> N=131072 tokens, D=256
//   embed_weight: [1024,256]    f32  -> K=1024 codes
// Outputs (f32): z_q_st [N*256], loss, perplexity, indices [N] (as float)
//
// Pipeline:
//   prep_cb:  normalize codebook -> g_bn (f32) + g_bh (fp16); zero stats
//   prep_zn:  normalize z per token -> g_zh (fp16)
//   vq_mma:   fp16 mma.sync argmax-GEMM, fp32 accum, exact top-2 per token,
//             gap < TAU -> flag for exact rescue
//   vq_rescue: exact fp32 re-argmax of flagged tokens (codebook streamed once
//              per block, f32x2 packed accumulation)
//   vq_out:   indices -> out, histogram, gather + STE + loss partials
//   finalize: loss & perplexity scalars
// ---------------------------------------------------------------------------

#define D_DIM 256
#define NTOK  131072
#define NCODE 1024
#define NBLK  (NTOK / 128)
#define TAU   7.5e-4f

// ---- static device scratch ----
__device__ __half g_zh[(size_t)NTOK * D_DIM];
__device__ __half g_bh[NCODE * D_DIM];
__device__ float  g_bn[NCODE * D_DIM];
__device__ int    g_idx[NTOK];
__device__ int    g_flags[NTOK];
__device__ int    g_flagcnt;
__device__ int    g_counts[NCODE];
__device__ float  g_partial[NBLK];

// ---- helpers ----
__device__ __forceinline__ void cp16(void* dst_smem, const void* src_gmem) {
    unsigned sdst = (unsigned)__cvta_generic_to_shared(dst_smem);
    asm volatile("cp.async.cg.shared.global [%0], [%1], 16;\n" :: "r"(sdst), "l"(src_gmem));
}
__device__ __forceinline__ void cp_commit() {
    asm volatile("cp.async.commit_group;\n" ::: "memory");
}
#define FMA2(ACC, AA, BB) \
    asm("fma.rn.f32x2 %0, %1, %2, %0;" : "+l"(ACC) : "l"(AA), "l"(BB))
__device__ __forceinline__ unsigned long long bcast2(float x) {
    unsigned long long r;
    asm("mov.b64 %0, {%1, %1};" : "=l"(r) : "r"(__float_as_uint(x)));
    return r;
}
__device__ __forceinline__ void mma16816(float* d, const uint32_t* a,
                                         uint32_t b0, uint32_t b1) {
    asm volatile(
        "mma.sync.aligned.m16n8k16.row.col.f32.f16.f16.f32 "
        "{%0,%1,%2,%3}, {%4,%5,%6,%7}, {%8,%9}, {%0,%1,%2,%3};"
        : "+f"(d[0]), "+f"(d[1]), "+f"(d[2]), "+f"(d[3])
        : "r"(a[0]), "r"(a[1]), "r"(a[2]), "r"(a[3]), "r"(b0), "r"(b1));
}

// ---------------- prep: codebook ----------------
__global__ void prep_cb(const float* __restrict__ w) {
    int k = blockIdx.x;
    int tid = threadIdx.x;   // 256 = D
    float v = w[(size_t)k * D_DIM + tid];
    float s = v * v;
    #pragma unroll
    for (int o = 16; o; o >>= 1) s += __shfl_xor_sync(0xffffffffu, s, o);
    __shared__ float ws[8];
    int lane = tid & 31, warp = tid >> 5;
    if (lane == 0) ws[warp] = s;
    __syncthreads();
    if (tid == 0) {
        float t = 0.f;
        #pragma unroll
        for (int i = 0; i < 8; i++) t += ws[i];
        ws[0] = t;
    }
    __syncthreads();
    float bn = v / fmaxf(sqrtf(ws[0]), 1e-12f);
    size_t o = (size_t)k * D_DIM + tid;
    g_bn[o] = bn;
    g_bh[o] = __float2half_rn(bn);
    if (tid == 0) g_counts[k] = 0;
    if (k == 0 && tid == 0) g_flagcnt = 0;
}

// ---------------- prep: z normalize + fp16 ----------------
__global__ __launch_bounds__(256)
void prep_zn(const float* __restrict__ z) {
    const int warp = threadIdx.x >> 5, lane = threadIdx.x & 31;
    const size_t tok = (size_t)blockIdx.x * 8 + warp;
    const float4* zr = (const float4*)(z + tok * D_DIM);
    float4 v0 = zr[lane], v1 = zr[lane + 32];
    float s = v0.x * v0.x + v0.y * v0.y + v0.z * v0.z + v0.w * v0.w
            + v1.x * v1.x + v1.y * v1.y + v1.z * v1.z + v1.w * v1.w;
    #pragma unroll
    for (int o = 16; o; o >>= 1) s += __shfl_xor_sync(0xffffffffu, s, o);
    float inv = 1.0f / fmaxf(sqrtf(s), 1e-12f);
    __half2* oh = (__half2*)(g_zh + tok * D_DIM);
    oh[lane * 2]      = __floats2half2_rn(v0.x * inv, v0.y * inv);
    oh[lane * 2 + 1]  = __floats2half2_rn(v0.z * inv, v0.w * inv);
    oh[64 + lane * 2]     = __floats2half2_rn(v1.x * inv, v1.y * inv);
    oh[64 + lane * 2 + 1] = __floats2half2_rn(v1.z * inv, v1.w * inv);
}

// ---------------- main: fp16 mma argmax-GEMM ----------------
// smem: A 128 rows x 132 words (pad 4) = 67584B; B double buffer 2x67584B
#define AROW 132
#define TILE_BYTES (128 * AROW * 4)
#define SMEM_MAIN (3 * TILE_BYTES)     // 202752

__global__ __launch_bounds__(256, 1)
void vq_mma() {
    extern __shared__ __align__(16) char smem[];
    uint32_t* As = (uint32_t*)smem;
    uint32_t* Bs = (uint32_t*)(smem + TILE_BYTES);

    const int tid = threadIdx.x;
    const int lane = tid & 31, warp = tid >> 5;
    const int wm = warp >> 1, wn = warp & 1;
    const int g = lane >> 2, kq = lane & 3;
    const int blk = blockIdx.x;

    // ---- prologue: load A (fp16 tokens) + B tile 0 ----
    {
        const __half* zsrc = g_zh + (size_t)blk * 128 * D_DIM;
        #pragma unroll
        for (int j = 0; j < 16; j++) {
            int m = tid + j * 256;
            int row = m >> 5, c = m & 31;
            cp16((char*)As + row * 528 + c * 16, zsrc + row * 256 + c * 8);
        }
        const __half* bsrc = g_bh;
        #pragma unroll
        for (int j = 0; j < 16; j++) {
            int m = tid + j * 256;
            int row = m >> 5, c = m & 31;
            cp16((char*)Bs + row * 528 + c * 16, bsrc + row * 256 + c * 8);
        }
        cp_commit();
        asm volatile("cp.async.wait_group 0;\n" ::: "memory");
        __syncthreads();
    }

    float best[4], best2[4];
    int   bidx[4];
    #pragma unroll
    for (int i = 0; i < 4; i++) { best[i] = -3.4e38f; best2[i] = -3.4e38f; bidx[i] = 0; }

    for (int ct = 0; ct < 8; ct++) {
        uint32_t* Bc = Bs + (ct & 1) * (TILE_BYTES / 4);

        // prefetch next B tile into the other buffer (its consumers synced last iter)
        if (ct < 7) {
            const __half* bsrc = g_bh + (size_t)(ct + 1) * 128 * D_DIM;
            char* dst = (char*)Bs + ((ct + 1) & 1) * TILE_BYTES;
            #pragma unroll
            for (int j = 0; j < 16; j++) {
                int m = tid + j * 256;
                int row = m >> 5, c = m & 31;
                cp16(dst + row * 528 + c * 16, bsrc + row * 256 + c * 8);
            }
            cp_commit();
        }

        float acc[2][8][4];
        #pragma unroll
        for (int mi = 0; mi < 2; mi++)
            #pragma unroll
            for (int ni = 0; ni < 8; ni++)
                #pragma unroll
                for (int c = 0; c < 4; c++) acc[mi][ni][c] = 0.f;

        #pragma unroll
        for (int ks = 0; ks < 16; ks++) {
            uint32_t a[2][4];
            #pragma unroll
            for (int mi = 0; mi < 2; mi++) {
                int r0 = (wm * 32 + mi * 16 + g) * AROW;
                int r1 = r0 + 8 * AROW;
                int w0 = ks * 8 + kq;
                a[mi][0] = As[r0 + w0];
                a[mi][1] = As[r1 + w0];
                a[mi][2] = As[r0 + w0 + 4];
                a[mi][3] = As[r1 + w0 + 4];
            }
            #pragma unroll
            for (int ni = 0; ni < 8; ni++) {
                int br = (wn * 64 + ni * 8 + g) * AROW + ks * 8 + kq;
                uint32_t b0 = Bc[br], b1 = Bc[br + 4];
                mma16816(acc[0][ni], a[0], b0, b1);
                mma16816(acc[1][ni], a[1], b0, b1);
            }
        }

        // fold this tile into running top-2 (per row instance)
        #pragma unroll
        for (int mi = 0; mi < 2; mi++)
            #pragma unroll
            for (int h = 0; h < 2; h++) {
                int ri = mi * 2 + h;
                #pragma unroll
                for (int ni = 0; ni < 8; ni++)
                    #pragma unroll
                    for (int c = 0; c < 2; c++) {
                        float v = acc[mi][ni][h * 2 + c];
                        int cb = ct * 128 + wn * 64 + ni * 8 + kq * 2 + c;
                        if (v > best[ri]) { best2[ri] = best[ri]; best[ri] = v; bidx[ri] = cb; }
                        else if (v > best2[ri]) best2[ri] = v;
                    }
            }

        if (ct < 7) {
            asm volatile("cp.async.wait_group 0;\n" ::: "memory");
            __syncthreads();
        }
    }

    // ---- cross-thread top-2 merge (8 threads per token) ----
    __syncthreads();
    float* rb  = (float*)smem;            // [128][8]
    float* rb2 = rb + 1024;               // [128][8]
    int*   rix = (int*)(rb2 + 1024);      // [128][8]
    const int slot = wn * 4 + kq;
    #pragma unroll
    for (int ri = 0; ri < 4; ri++) {
        int row = wm * 32 + (ri >> 1) * 16 + (ri & 1) * 8 + g;
        rb [row * 8 + slot] = best[ri];
        rb2[row * 8 + slot] = best2[ri];
        rix[row * 8 + slot] = bidx[ri];
    }
    __syncthreads();
    if (tid < 128) {
        float B = rb[tid * 8], B2 = rb2[tid * 8];
        int   I = rix[tid * 8];
        #pragma unroll
        for (int s = 1; s < 8; s++) {
            float b = rb[tid * 8 + s], b2s = rb2[tid * 8 + s];
            int   i = rix[tid * 8 + s];
            if (b > B || (b == B && i < I)) {
                B2 = fmaxf(fmaxf(B, b2s), B2);
                B = b; I = i;
            } else {
                B2 = fmaxf(B2, b);
            }
        }
        int tok = blk * 128 + tid;
        g_idx[tok] = I;
        if (B - B2 < TAU) {
            int sl = atomicAdd(&g_flagcnt, 1);
            g_flags[sl] = tok;
        }
    }
}

// ---------------- rescue: exact fp32 re-argmax of flagged tokens ----------------
// Block handles 16 tokens; codebook streamed once per block (each thread owns
// 4 code rows); z rows transposed in smem, broadcast reads; f32x2 accumulation.
__global__ __launch_bounds__(256)
void vq_rescue(const float* __restrict__ z) {
    __shared__ __align__(8) float zs[D_DIM][16];
    __shared__ int stoks[16];
    __shared__ float wrb[8][16];
    __shared__ int   wri[8][16];
    const int tid = threadIdx.x, lane = tid & 31, warp = tid >> 5;
    const int nf = g_flagcnt;

    for (int base = blockIdx.x * 16; base < nf; base += gridDim.x * 16) {
        const int vcnt = min(16, nf - base);
        if (tid < 16) stoks[tid] = g_flags[base + (tid < vcnt ? tid : 0)];
        __syncthreads();
        // load z rows transposed: zs[d][t]
        {
            int tt = tid >> 4, dc = tid & 15;
            const float4* zr = (const float4*)(z + (size_t)stoks[tt] * D_DIM) + dc * 4;
            #pragma unroll
            for (int q = 0; q < 4; q++) {
                float4 v = zr[q];
                int d = dc * 16 + q * 4;
                zs[d][tt] = v.x; zs[d + 1][tt] = v.y;
                zs[d + 2][tt] = v.z; zs[d + 3][tt] = v.w;
            }
        }
        __syncthreads();

        unsigned long long acc[4][8];
        #pragma unroll
        for (int j = 0; j < 4; j++)
            #pragma unroll
            for (int p = 0; p < 8; p++) acc[j][p] = 0ull;

        const float4* c0p = (const float4*)(g_bn + (size_t)(4 * tid + 0) * D_DIM);
        const float4* c1p = (const float4*)(g_bn + (size_t)(4 * tid + 1) * D_DIM);
        const float4* c2p = (const float4*)(g_bn + (size_t)(4 * tid + 2) * D_DIM);
        const float4* c3p = (const float4*)(g_bn + (size_t)(4 * tid + 3) * D_DIM);

        for (int dq = 0; dq < 64; dq++) {
            float4 v0 = c0p[dq], v1 = c1p[dq], v2 = c2p[dq], v3 = c3p[dq];
            float ca[4][4] = {{v0.x, v0.y, v0.z, v0.w}, {v1.x, v1.y, v1.z, v1.w},
                              {v2.x, v2.y, v2.z, v2.w}, {v3.x, v3.y, v3.z, v3.w}};
            #pragma unroll
            for (int dd = 0; dd < 4; dd++) {
                int d = dq * 4 + dd;
                const unsigned long long* zrow = (const unsigned long long*)&zs[d][0];
                unsigned long long zp[8];
                #pragma unroll
                for (int p = 0; p < 8; p++) zp[p] = zrow[p];
                #pragma unroll
                for (int j = 0; j < 4; j++) {
                    unsigned long long bc = bcast2(ca[j][dd]);
                    #pragma unroll
                    for (int p = 0; p < 8; p++) FMA2(acc[j][p], zp[p], bc);
                }
            }
        }

        // per-thread argmax over its 4 codes for each of 16 tokens
        float lb[16]; int li[16];
        #pragma unroll
        for (int t = 0; t < 16; t++) { lb[t] = -3.4e38f; li[t] = 0x7fffffff; }
        #pragma unroll
        for (int j = 0; j < 4; j++) {
            int cidx = tid * 4 + j;
            #pragma unroll
            for (int p = 0; p < 8; p++) {
                float lo = __uint_as_float((unsigned)(acc[j][p] & 0xffffffffull));
                float hi = __uint_as_float((unsigned)(acc[j][p] >> 32));
                int t0 = 2 * p, t1 = 2 * p + 1;
                if (lo > lb[t0] || (lo == lb[t0] && cidx < li[t0])) { lb[t0] = lo; li[t0] = cidx; }
                if (hi > lb[t1] || (hi == lb[t1] && cidx < li[t1])) { lb[t1] = hi; li[t1] = cidx; }
            }
        }
        // warp reduce per token
        #pragma unroll
        for (int t = 0; t < 16; t++) {
            float b = lb[t]; int i = li[t];
            #pragma unroll
            for (int off = 16; off; off >>= 1) {
                float ob = __shfl_xor_sync(0xffffffffu, b, off);
                int   oi = __shfl_xor_sync(0xffffffffu, i, off);
                if (ob > b || (ob == b && oi < i)) { b = ob; i = oi; }
            }
            if (lane == 0) { wrb[warp][t] = b; wri[warp][t] = i; }
        }
        __syncthreads();
        if (tid < 16) {
            float b = wrb[0][tid]; int i = wri[0][tid];
            #pragma unroll
            for (int w = 1; w < 8; w++) {
                float ob = wrb[w][tid]; int oi = wri[w][tid];
                if (ob > b || (ob == b && oi < i)) { b = ob; i = oi; }
            }
            if (tid < vcnt) g_idx[stoks[tid]] = i;
        }
        __syncthreads();
    }
}

// ---------------- output pass: idx -> out, hist, gather + STE + loss ----------------
__global__ __launch_bounds__(256)
void vq_out(const float* __restrict__ z, const float* __restrict__ w,
            float* __restrict__ out_zq, float* __restrict__ out_idx) {
    __shared__ int   idx_s[128];
    __shared__ float red_s[8];
    const int tid = threadIdx.x;
    const int blk = blockIdx.x;
    const int lane = tid & 31, warp = tid >> 5;

    if (tid < 128) {
        int gi = g_idx[blk * 128 + tid];
        idx_s[tid] = gi;
        out_idx[blk * 128 + tid] = (float)gi;
        atomicAdd(&g_counts[gi], 1);
    }
    __syncthreads();

    float ls = 0.f;
    {
        const int t = tid >> 1, dh = tid & 1;
        const int gi = idx_s[t];
        const float4* wrow = (const float4*)(w + (size_t)gi * D_DIM + dh * 128);
        const float4* zrow = (const float4*)(z + ((size_t)blk * 128 + t) * D_DIM + dh * 128);
        float4* orow = (float4*)(out_zq + ((size_t)blk * 128 + t) * D_DIM + dh * 128);
        #pragma unroll
        for (int i = 0; i < 32; i++) {
            float4 q = wrow[i];
            float4 zv = zrow[i];
            float e0 = q.x - zv.x, e1 = q.y - zv.y, e2 = q.z - zv.z, e3 = q.w - zv.w;
            float4 o; o.x = zv.x + e0; o.y = zv.y + e1; o.z = zv.z + e2; o.w = zv.w + e3;
            orow[i] = o;
            ls += e0 * e0 + e1 * e1 + e2 * e2 + e3 * e3;
        }
    }
    #pragma unroll
    for (int o = 16; o; o >>= 1) ls += __shfl_xor_sync(0xffffffffu, ls, o);
    if (lane == 0) red_s[warp] = ls;
    __syncthreads();
    if (tid == 0) {
        float t = 0.f;
        #pragma unroll
        for (int i = 0; i < 8; i++) t += red_s[i];
        g_partial[blk] = t;
    }
}

// ---------------- finalize: loss + perplexity ----------------
__global__ void finalize_kernel(float* __restrict__ out_sc, int N, int K, int nblk) {
    __shared__ float sh[1024];
    int tid = threadIdx.x;
    float s = (tid < nblk) ? g_partial[tid] : 0.f;
    sh[tid] = s;
    __syncthreads();
    for (int st = 512; st; st >>= 1) {
        if (tid < st) sh[tid] += sh[tid + st];
        __syncthreads();
    }
    float S = sh[0];
    __syncthreads();
    float e = 0.f;
    if (tid < K) {
        float p = (float)g_counts[tid] / (float)N;
        e = p * logf(p + 1e-10f);
    }
    sh[tid] = e;
    __syncthreads();
    for (int st = 512; st; st >>= 1) {
        if (tid < st) sh[tid] += sh[tid + st];
        __syncthreads();
    }
    if (tid == 0) {
        out_sc[0] = 1.25f * S / ((float)N * (float)D_DIM);
        out_sc[1] = expf(-sh[0]);
    }
}

// ---------------- launch ----------------
extern "C" void kernel_launch(void* const* d_in, const int* in_sizes, int n_in,
                              void* d_out, int out_size) {
    const float* z = (const float*)d_in[0];
    const float* w = (const float*)d_in[1];
    const int n_z = in_sizes[0];          // N * 256
    const int N = n_z / D_DIM;
    const int nblk = N / 128;

    float* out = (float*)d_out;
    float* out_zq  = out;
    float* out_sc  = out + n_z;
    float* out_idx = out + n_z + 2;

    prep_cb<<<NCODE, 256>>>(w);
    prep_zn<<<N / 8, 256>>>(z);

    cudaFuncSetAttribute(vq_mma, cudaFuncAttributeMaxDynamicSharedMemorySize, SMEM_MAIN);
    vq_mma<<<nblk, 256, SMEM_MAIN>>>();

    vq_rescue<<<256, 256>>>(z);
    vq_out<<<nblk, 256>>>(z, w, out_zq, out_idx);
    finalize_kernel<<<1, 1024>>>(out_sc, N, NCODE, nblk);
}